// round 1
// baseline (speedup 1.0000x reference)
#include <cuda_runtime.h>

// Problem constants (fixed by setup_inputs: H=480, W=1024, S=32, margin=10, step=4)
#define HH     480
#define WW     1024
#define SS     32
#define HWIMG  (HH*WW)          // 491520
#define NSLOT  61440            // 2*H*W/step^2
#define GXC    252              // len(arange(10, 1015, 4))
#define GYC    116              // len(arange(10, 471, 4))
#define GG     (GXC*GYC)        // 29232
#define MARG   10
#define SLOTBLK 60              // 60*1024 == NSLOT
#define CANDBLK 29              // ceil(GG/1024)

// Scratch (device globals; no allocations allowed)
__device__ unsigned char g_occ[GG];
__device__ int g_slotList[NSLOT];
__device__ int g_candList[GG];
__device__ int g_slotCnt[SLOTBLK];
__device__ int g_candCnt[CANDBLK];

// 4-term bilinear combine, replicating XLA/NVPTX aggressive-FMA fusion of
// ((s00*w00 + s01*w01) + s10*w10) + s11*w11
__device__ __forceinline__ float bil4(float s00, float s01, float s10, float s11,
                                      float w00, float w01, float w10, float w11) {
    return fmaf(s11, w11, fmaf(s10, w10, fmaf(s00, w00, __fmul_rn(s01, w01))));
}

struct BilW {
    int ix0, ix1, iy0, iy1;
    float w00, w01, w10, w11;
};

// Weights from UNCLIPPED coords, gather indices clipped (torch bilinear_sample2d semantics)
__device__ __forceinline__ BilW mkw(float x, float y) {
    BilW b;
    float x0f = floorf(x), y0f = floorf(y);
    float wx1 = __fsub_rn(x, x0f); float wx0 = __fsub_rn(1.0f, wx1);
    float wy1 = __fsub_rn(y, y0f); float wy0 = __fsub_rn(1.0f, wy1);
    int ix0 = (int)x0f; ix0 = ix0 < 0 ? 0 : (ix0 > WW-1 ? WW-1 : ix0);
    int iy0 = (int)y0f; iy0 = iy0 < 0 ? 0 : (iy0 > HH-1 ? HH-1 : iy0);
    b.ix0 = ix0; b.ix1 = (ix0+1 > WW-1) ? WW-1 : ix0+1;
    b.iy0 = iy0; b.iy1 = (iy0+1 > HH-1) ? HH-1 : iy0+1;
    b.w00 = __fmul_rn(wy0, wx0); b.w01 = __fmul_rn(wy0, wx1);
    b.w10 = __fmul_rn(wy1, wx0); b.w11 = __fmul_rn(wy1, wx1);
    return b;
}

// On-demand fwd-bwd consistency value at integer pixel (py,px).
// a0,a1 = flow_f at that pixel (already loaded as a uv-sampling corner).
__device__ __forceinline__ float on_at(const float* __restrict__ fb0,
                                       const float* __restrict__ fb1,
                                       float a0, float a1, int py, int px) {
    float xt = __fadd_rn((float)px, a0);
    float yt = __fadd_rn((float)py, a1);
    BilW b = mkw(xt, yt);
    float f00 = fb0[b.iy0*WW+b.ix0], f01 = fb0[b.iy0*WW+b.ix1];
    float f10 = fb0[b.iy1*WW+b.ix0], f11 = fb0[b.iy1*WW+b.ix1];
    float g00 = fb1[b.iy0*WW+b.ix0], g01 = fb1[b.iy0*WW+b.ix1];
    float g10 = fb1[b.iy1*WW+b.ix0], g11 = fb1[b.iy1*WW+b.ix1];
    float f0 = bil4(f00, f01, f10, f11, b.w00, b.w01, b.w10, b.w11);
    float f1 = bil4(g00, g01, g10, g11, b.w00, b.w01, b.w10, b.w11);
    float d0 = __fadd_rn(a0, f0), d1 = __fadd_rn(a1, f1);
    float diff = __fsqrt_rn(fmaf(d1, d1, __fmul_rn(d0, d0)));
    float m1 = __fsqrt_rn(fmaf(a1, a1, __fmul_rn(a0, a0)));
    float m2 = __fsqrt_rn(fmaf(f1, f1, __fmul_rn(f0, f0)));
    float mag = __fmul_rn(0.5f, __fadd_rn(m1, m2));
    return (diff <= fmaf(0.01f, mag, 0.1f)) ? 1.0f : 0.0f;
}

// ---------------- init ----------------
__global__ void k_init(float* __restrict__ out) {
    int n = blockIdx.x * 1024 + threadIdx.x;
    if (n < NSLOT) {
        bool ing = n < GG;
        out[n]                 = ing ? (float)(MARG + 4*(n % GXC)) : 0.0f;   // X[0]
        out[SS*NSLOT + n]      = ing ? (float)(MARG + 4*(n / GXC)) : 0.0f;   // Y[0]
        out[2*SS*NSLOT + n]    = ing ? 0.0f : -1.0f;                          // Start
    }
    if (n < GG) g_occ[n] = 0;
}

// ---------------- K1: advance slots, write row s+1, update Start, mark occ ----------------
__global__ void __launch_bounds__(1024) k_advance(const float* __restrict__ ff,
                                                  const float* __restrict__ fb,
                                                  float* __restrict__ out, int s) {
    int n = blockIdx.x * 1024 + threadIdx.x;
    float* X  = out;
    float* Y  = out + SS*NSLOT;
    float* St = out + 2*SS*NSLOT;
    const float* ff0 = ff + (size_t)s * 2 * HWIMG;
    const float* ff1 = ff0 + HWIMG;
    const float* fb0 = fb + (size_t)s * 2 * HWIMG;
    const float* fb1 = fb0 + HWIMG;

    bool freeflag = true;   // == (updated Start < 0) == !choose
    float xw = 0.0f, yw = 0.0f;
    float start = St[n];
    if (start >= 0.0f) {
        float x = X[s*NSLOT + n], y = Y[s*NSLOT + n];
        BilW b = mkw(x, y);
        float u00 = ff0[b.iy0*WW+b.ix0], u01 = ff0[b.iy0*WW+b.ix1];
        float u10 = ff0[b.iy1*WW+b.ix0], u11 = ff0[b.iy1*WW+b.ix1];
        float v00 = ff1[b.iy0*WW+b.ix0], v01 = ff1[b.iy0*WW+b.ix1];
        float v10 = ff1[b.iy1*WW+b.ix0], v11 = ff1[b.iy1*WW+b.ix1];
        float uvx = bil4(u00, u01, u10, u11, b.w00, b.w01, b.w10, b.w11);
        float uvy = bil4(v00, v01, v10, v11, b.w00, b.w01, b.w10, b.w11);
        float xt = __fadd_rn(x, uvx);
        float yt = __fadd_rn(y, uvy);
        bool marg = (xt > (float)MARG) && (yt > (float)MARG) &&
                    (xt < (float)(WW - MARG)) && (yt < (float)(HH - MARG));
        if (marg) {
            // corners with weight exactly 0 contribute fmaf(s,0,acc)==acc: skip safely
            float on00 = (b.w00 != 0.0f) ? on_at(fb0, fb1, u00, v00, b.iy0, b.ix0) : 0.0f;
            float on01 = (b.w01 != 0.0f) ? on_at(fb0, fb1, u01, v01, b.iy0, b.ix1) : 0.0f;
            float on10 = (b.w10 != 0.0f) ? on_at(fb0, fb1, u10, v10, b.iy1, b.ix0) : 0.0f;
            float on11 = (b.w11 != 0.0f) ? on_at(fb0, fb1, u11, v11, b.iy1, b.ix1) : 0.0f;
            float onv = bil4(on00, on01, on10, on11, b.w00, b.w01, b.w10, b.w11);
            if (onv > 0.5f) {
                freeflag = false;
                xw = xt; yw = yt;
                // occupancy: survivor (trunc coords) covers grid cells within +-2
                int oy = (int)yt, ox = (int)xt;            // positive -> trunc == floor
                int iylo = (oy - 9) / 4; if (iylo < 0) iylo = 0;
                int iyhi = (oy - 8) / 4; if (iyhi > GYC-1) iyhi = GYC-1;
                int ixlo = (ox - 9) / 4; if (ixlo < 0) ixlo = 0;
                int ixhi = (ox - 8) / 4; if (ixhi > GXC-1) ixhi = GXC-1;
                for (int iy = iylo; iy <= iyhi; iy++)
                    for (int ix = ixlo; ix <= ixhi; ix++)
                        g_occ[iy*GXC + ix] = 1;            // idempotent stores
            }
        }
        if (freeflag) St[n] = -1.0f;   // active & !choose -> terminated
    }
    X[(s+1)*NSLOT + n] = xw;
    Y[(s+1)*NSLOT + n] = yw;

    // deterministic per-block free-slot count
    __shared__ int s_cnt;
    if (threadIdx.x == 0) s_cnt = 0;
    __syncthreads();
    unsigned mask = __ballot_sync(0xffffffffu, freeflag);
    if ((threadIdx.x & 31) == 0) atomicAdd(&s_cnt, __popc(mask));
    __syncthreads();
    if (threadIdx.x == 0) g_slotCnt[blockIdx.x] = s_cnt;
}

// ---------------- K2: per-block free-candidate counts ----------------
__global__ void k_candcnt() {
    int g = blockIdx.x * 1024 + threadIdx.x;
    bool flag = (g < GG) && (g_occ[g] == 0);
    __shared__ int s_cnt;
    if (threadIdx.x == 0) s_cnt = 0;
    __syncthreads();
    unsigned mask = __ballot_sync(0xffffffffu, flag);
    if ((threadIdx.x & 31) == 0) atomicAdd(&s_cnt, __popc(mask));
    __syncthreads();
    if (threadIdx.x == 0) g_candCnt[blockIdx.x] = s_cnt;
}

// ---------------- K3: ordered compaction into slot/cand lists ----------------
__global__ void __launch_bounds__(1024) k_lists(const float* __restrict__ out) {
    int tid = threadIdx.x;
    int lane = tid & 31, wid = tid >> 5;
    __shared__ int s_base;
    __shared__ int wcnt[32];
    if (tid == 0) s_base = 0;
    __syncthreads();

    bool flag; int idx; int* list;
    if (blockIdx.x < SLOTBLK) {
        const float* St = out + 2*SS*NSLOT;
        idx = blockIdx.x * 1024 + tid;
        flag = St[idx] < 0.0f;
        if (tid < (int)blockIdx.x) atomicAdd(&s_base, g_slotCnt[tid]);
        list = g_slotList;
    } else {
        int cb = blockIdx.x - SLOTBLK;
        idx = cb * 1024 + tid;
        flag = (idx < GG) && (g_occ[idx] == 0);
        if (tid < cb) atomicAdd(&s_base, g_candCnt[tid]);
        list = g_candList;
    }
    unsigned mask = __ballot_sync(0xffffffffu, flag);
    if (lane == 0) wcnt[wid] = __popc(mask);
    __syncthreads();
    if (tid == 0) {
        int run = 0;
        for (int i = 0; i < 32; i++) { int c = wcnt[i]; wcnt[i] = run; run += c; }
    }
    __syncthreads();
    if (flag) {
        int rank = wcnt[wid] + __popc(mask & ((1u << lane) - 1u));
        list[s_base + rank] = idx;
    }
}

// ---------------- K4: births (k-th free cand -> k-th free slot) + clear occ ----------------
__global__ void k_birth(float* __restrict__ out, int s) {
    __shared__ int s_nf, s_nc;
    int tid = threadIdx.x;
    if (tid == 0) { s_nf = 0; s_nc = 0; }
    __syncthreads();
    if (tid < SLOTBLK)                    atomicAdd(&s_nf, g_slotCnt[tid]);
    else if (tid < SLOTBLK + CANDBLK)     atomicAdd(&s_nc, g_candCnt[tid - SLOTBLK]);
    __syncthreads();
    int m = s_nf < s_nc ? s_nf : s_nc;
    int r = blockIdx.x * 1024 + tid;
    if (r < m) {
        int slot = g_slotList[r];
        int g = g_candList[r];
        int iy = g / GXC, ix = g % GXC;
        out[(s+1)*NSLOT + slot]             = (float)(MARG + 4*ix);
        out[SS*NSLOT + (s+1)*NSLOT + slot]  = (float)(MARG + 4*iy);
        out[2*SS*NSLOT + slot]              = (float)(s + 1);
    }
    if (r < GG) g_occ[r] = 0;   // ready for next step's marking
}

extern "C" void kernel_launch(void* const* d_in, const int* in_sizes, int n_in,
                              void* d_out, int out_size) {
    (void)in_sizes; (void)n_in; (void)out_size;
    const float* ff = (const float*)d_in[0];
    const float* fb = (const float*)d_in[1];
    float* out = (float*)d_out;

    k_init<<<SLOTBLK, 1024>>>(out);
    for (int s = 0; s < SS - 1; s++) {
        k_advance<<<SLOTBLK, 1024>>>(ff, fb, out, s);
        k_candcnt<<<CANDBLK, 1024>>>();
        k_lists<<<SLOTBLK + CANDBLK, 1024>>>(out);
        k_birth<<<CANDBLK, 1024>>>(out, s);
    }
}

// round 2
// speedup vs baseline: 1.0224x; 1.0224x over previous
#include <cuda_runtime.h>

// Problem constants (fixed by setup_inputs: H=480, W=1024, S=32, margin=10, step=4)
#define HH     480
#define WW     1024
#define SS     32
#define HWIMG  (HH*WW)          // 491520
#define NSLOT  61440            // 2*H*W/step^2
#define GXC    252
#define GYC    116
#define GG     (GXC*GYC)        // 29232
#define MARG   10
#define BB     120              // persistent grid: 120 blocks x 512 = NSLOT threads
#define TT     512
#define NCANDB 58               // blocks whose thread range intersects [0, GG)

// Scratch (device globals; no allocations allowed)
__device__ __align__(16) unsigned char g_occ[GG];   // zero at load; invariant: zero at kernel exit
__device__ int g_slotList[NSLOT];
__device__ int g_candList[GG];
__device__ int g_slotCnt[BB];
__device__ int g_nc;
__device__ unsigned g_barCnt = 0;
__device__ volatile unsigned g_barGen = 0;

__device__ __forceinline__ void gridbar() {
    __syncthreads();
    if (threadIdx.x == 0) {
        __threadfence();                       // release: publish this block's writes
        unsigned gen = g_barGen;
        if (atomicAdd(&g_barCnt, 1u) == BB - 1u) {
            atomicExch(&g_barCnt, 0u);
            __threadfence();
            g_barGen = gen + 1u;
        } else {
            while (g_barGen == gen) { }
        }
    }
    __syncthreads();
}

// ---- math helpers: byte-identical to the R1 kernel (rel_err was 0.0) ----
__device__ __forceinline__ float bil4(float s00, float s01, float s10, float s11,
                                      float w00, float w01, float w10, float w11) {
    return fmaf(s11, w11, fmaf(s10, w10, fmaf(s00, w00, __fmul_rn(s01, w01))));
}

struct BilW {
    int ix0, ix1, iy0, iy1;
    float w00, w01, w10, w11;
};

__device__ __forceinline__ BilW mkw(float x, float y) {
    BilW b;
    float x0f = floorf(x), y0f = floorf(y);
    float wx1 = __fsub_rn(x, x0f); float wx0 = __fsub_rn(1.0f, wx1);
    float wy1 = __fsub_rn(y, y0f); float wy0 = __fsub_rn(1.0f, wy1);
    int ix0 = (int)x0f; ix0 = ix0 < 0 ? 0 : (ix0 > WW-1 ? WW-1 : ix0);
    int iy0 = (int)y0f; iy0 = iy0 < 0 ? 0 : (iy0 > HH-1 ? HH-1 : iy0);
    b.ix0 = ix0; b.ix1 = (ix0+1 > WW-1) ? WW-1 : ix0+1;
    b.iy0 = iy0; b.iy1 = (iy0+1 > HH-1) ? HH-1 : iy0+1;
    b.w00 = __fmul_rn(wy0, wx0); b.w01 = __fmul_rn(wy0, wx1);
    b.w10 = __fmul_rn(wy1, wx0); b.w11 = __fmul_rn(wy1, wx1);
    return b;
}

__device__ __forceinline__ float on_at(const float* __restrict__ fb0,
                                       const float* __restrict__ fb1,
                                       float a0, float a1, int py, int px) {
    float xt = __fadd_rn((float)px, a0);
    float yt = __fadd_rn((float)py, a1);
    BilW b = mkw(xt, yt);
    float f00 = fb0[b.iy0*WW+b.ix0], f01 = fb0[b.iy0*WW+b.ix1];
    float f10 = fb0[b.iy1*WW+b.ix0], f11 = fb0[b.iy1*WW+b.ix1];
    float g00 = fb1[b.iy0*WW+b.ix0], g01 = fb1[b.iy0*WW+b.ix1];
    float g10 = fb1[b.iy1*WW+b.ix0], g11 = fb1[b.iy1*WW+b.ix1];
    float f0 = bil4(f00, f01, f10, f11, b.w00, b.w01, b.w10, b.w11);
    float f1 = bil4(g00, g01, g10, g11, b.w00, b.w01, b.w10, b.w11);
    float d0 = __fadd_rn(a0, f0), d1 = __fadd_rn(a1, f1);
    float diff = __fsqrt_rn(fmaf(d1, d1, __fmul_rn(d0, d0)));
    float m1 = __fsqrt_rn(fmaf(a1, a1, __fmul_rn(a0, a0)));
    float m2 = __fsqrt_rn(fmaf(f1, f1, __fmul_rn(f0, f0)));
    float mag = __fmul_rn(0.5f, __fadd_rn(m1, m2));
    return (diff <= fmaf(0.01f, mag, 0.1f)) ? 1.0f : 0.0f;
}

// ---------------- one persistent kernel for the whole scan ----------------
__global__ void __launch_bounds__(TT, 1) k_linker(const float* __restrict__ ff,
                                                  const float* __restrict__ fb,
                                                  float* __restrict__ out) {
    const int tid  = threadIdx.x;
    const int b    = blockIdx.x;
    const int lane = tid & 31;
    const int wid  = tid >> 5;
    const int t    = b * TT + tid;         // slot id (0..NSLOT-1), also cand id if < GG

    float* X  = out;
    float* Y  = out + SS*NSLOT;
    float* St = out + 2*SS*NSLOT;

    __shared__ int sh_cnt;
    __shared__ int sh_slotBase, sh_candBase, sh_nf;
    __shared__ int sh_w[16], sh_c[16];

    // ---- init (all reads of these values in step 0 are by the same thread) ----
    {
        bool ing = t < GG;
        X[t]  = ing ? (float)(MARG + 4*(t % GXC)) : 0.0f;
        Y[t]  = ing ? (float)(MARG + 4*(t / GXC)) : 0.0f;
        St[t] = ing ? 0.0f : -1.0f;
    }

    for (int s = 0; s < SS - 1; s++) {
        const float* ff0 = ff + (size_t)s * 2 * HWIMG;
        const float* ff1 = ff0 + HWIMG;
        const float* fb0 = fb + (size_t)s * 2 * HWIMG;
        const float* fb1 = fb0 + HWIMG;

        // ================= Phase A: advance, mark occ, count free slots =================
        bool freeflag = true;                 // == (updated Start < 0)
        float xw = 0.0f, yw = 0.0f;
        float start = __ldcg(&St[t]);
        if (start >= 0.0f) {
            float x = __ldcg(&X[s*NSLOT + t]);
            float y = __ldcg(&Y[s*NSLOT + t]);
            BilW bw = mkw(x, y);
            float u00 = ff0[bw.iy0*WW+bw.ix0], u01 = ff0[bw.iy0*WW+bw.ix1];
            float u10 = ff0[bw.iy1*WW+bw.ix0], u11 = ff0[bw.iy1*WW+bw.ix1];
            float v00 = ff1[bw.iy0*WW+bw.ix0], v01 = ff1[bw.iy0*WW+bw.ix1];
            float v10 = ff1[bw.iy1*WW+bw.ix0], v11 = ff1[bw.iy1*WW+bw.ix1];
            float uvx = bil4(u00, u01, u10, u11, bw.w00, bw.w01, bw.w10, bw.w11);
            float uvy = bil4(v00, v01, v10, v11, bw.w00, bw.w01, bw.w10, bw.w11);
            float xt = __fadd_rn(x, uvx);
            float yt = __fadd_rn(y, uvy);
            bool marg = (xt > (float)MARG) && (yt > (float)MARG) &&
                        (xt < (float)(WW - MARG)) && (yt < (float)(HH - MARG));
            if (marg) {
                float on00 = (bw.w00 != 0.0f) ? on_at(fb0, fb1, u00, v00, bw.iy0, bw.ix0) : 0.0f;
                float on01 = (bw.w01 != 0.0f) ? on_at(fb0, fb1, u01, v01, bw.iy0, bw.ix1) : 0.0f;
                float on10 = (bw.w10 != 0.0f) ? on_at(fb0, fb1, u10, v10, bw.iy1, bw.ix0) : 0.0f;
                float on11 = (bw.w11 != 0.0f) ? on_at(fb0, fb1, u11, v11, bw.iy1, bw.ix1) : 0.0f;
                float onv = bil4(on00, on01, on10, on11, bw.w00, bw.w01, bw.w10, bw.w11);
                if (onv > 0.5f) {
                    freeflag = false;
                    xw = xt; yw = yt;
                    int oy = (int)yt, ox = (int)xt;
                    int iylo = (oy - 9) / 4; if (iylo < 0) iylo = 0;
                    int iyhi = (oy - 8) / 4; if (iyhi > GYC-1) iyhi = GYC-1;
                    int ixlo = (ox - 9) / 4; if (ixlo < 0) ixlo = 0;
                    int ixhi = (ox - 8) / 4; if (ixhi > GXC-1) ixhi = GXC-1;
                    for (int iy = iylo; iy <= iyhi; iy++)
                        for (int ix = ixlo; ix <= ixhi; ix++)
                            g_occ[iy*GXC + ix] = 1;        // idempotent
                }
            }
            if (freeflag) St[t] = -1.0f;
        }
        X[(s+1)*NSLOT + t] = xw;
        Y[(s+1)*NSLOT + t] = yw;

        if (tid == 0) sh_cnt = 0;
        __syncthreads();
        unsigned amask = __ballot_sync(0xffffffffu, freeflag);
        if (lane == 0) atomicAdd(&sh_cnt, __popc(amask));
        __syncthreads();
        if (tid == 0) g_slotCnt[b] = sh_cnt;

        gridbar();   // occ + slot counts + row s+1 visible

        // ================= Phase B: ordered compaction of free slots & candidates =================
        if (tid == 0) { sh_slotBase = 0; sh_candBase = 0; }
        __syncthreads();
        if (tid < b) atomicAdd(&sh_slotBase, __ldcg(&g_slotCnt[tid]));
        unsigned smask = __ballot_sync(0xffffffffu, freeflag);
        if (lane == 0) sh_w[wid] = __popc(smask);

        bool cf = false;
        unsigned cmask = 0;
        if (b < NCANDB) {
            if (t < GG) cf = (__ldcg(&g_occ[t]) == 0);
            // candidate base for this block: zeros in occ[0 .. b*TT)  (b*TT <= 29184 < GG)
            int pre = b * TT;
            int zbits = 0;
            for (int i = tid * 16; i < pre; i += TT * 16) {
                uint4 v = __ldcg((const uint4*)(g_occ + i));
                zbits += __popc(__vcmpeq4(v.x, 0u)) + __popc(__vcmpeq4(v.y, 0u))
                       + __popc(__vcmpeq4(v.z, 0u)) + __popc(__vcmpeq4(v.w, 0u));
            }
            zbits = __reduce_add_sync(0xffffffffu, zbits);
            if (lane == 0 && zbits) atomicAdd(&sh_candBase, zbits >> 3);
            cmask = __ballot_sync(0xffffffffu, cf);
            if (lane == 0) sh_c[wid] = __popc(cmask);
        }
        __syncthreads();
        if (tid == 0) {
            int run = sh_slotBase;
            for (int i = 0; i < 16; i++) { int c = sh_w[i]; sh_w[i] = run; run += c; }
            if (b < NCANDB) {
                int crun = sh_candBase;
                for (int i = 0; i < 16; i++) { int c = sh_c[i]; sh_c[i] = crun; crun += c; }
                if (b == NCANDB - 1) g_nc = crun;     // total free candidates
            }
        }
        __syncthreads();
        if (freeflag)
            g_slotList[sh_w[wid] + __popc(smask & ((1u << lane) - 1u))] = t;
        if (cf)
            g_candList[sh_c[wid] + __popc(cmask & ((1u << lane) - 1u))] = t;

        gridbar();   // lists + g_nc visible

        // ================= Phase C: births (k-th free cand -> k-th free slot) + clear occ =================
        if (tid == 0) sh_nf = 0;
        __syncthreads();
        if (tid < BB) atomicAdd(&sh_nf, __ldcg(&g_slotCnt[tid]));
        __syncthreads();
        int nf = sh_nf;
        int nc = __ldcg(&g_nc);
        int m = nf < nc ? nf : nc;
        if (t < m) {
            int slot = __ldcg(&g_slotList[t]);
            int g    = __ldcg(&g_candList[t]);
            int iy = g / GXC, ix = g % GXC;
            X[(s+1)*NSLOT + slot] = (float)(MARG + 4*ix);
            Y[(s+1)*NSLOT + slot] = (float)(MARG + 4*iy);
            St[slot]              = (float)(s + 1);
        }
        if (t < GG) g_occ[t] = 0;   // restore zero-invariant for next step / next replay

        gridbar();   // births + cleared occ visible before next step's Phase A
    }
}

extern "C" void kernel_launch(void* const* d_in, const int* in_sizes, int n_in,
                              void* d_out, int out_size) {
    (void)in_sizes; (void)n_in; (void)out_size;
    const float* ff = (const float*)d_in[0];
    const float* fb = (const float*)d_in[1];
    float* out = (float*)d_out;
    k_linker<<<BB, TT>>>(ff, fb, out);
}

// round 3
// speedup vs baseline: 1.1131x; 1.0886x over previous
#include <cuda_runtime.h>

// Problem constants (fixed by setup_inputs: H=480, W=1024, S=32, margin=10, step=4)
#define HH     480
#define WW     1024
#define SS     32
#define HWIMG  (HH*WW)          // 491520
#define NSLOT  61440            // 2*H*W/step^2
#define GXC    252
#define GYC    116
#define GG     (GXC*GYC)        // 29232
#define MARG   10
#define BB     480              // persistent grid: 480 blocks x 128 = NSLOT threads
#define TT     128
#define NCANDB 229              // ceil(GG / TT)

// Scratch (device globals; no allocations allowed)
__device__ __align__(16) unsigned char g_occ[2][GG];  // double-buffered by step parity; zero at load & exit
__device__ int g_candList[GG];
__device__ int g_slotCnt[BB];
__device__ int g_nc;
__device__ unsigned g_barCnt = 0;
__device__ volatile unsigned g_barGen = 0;

__device__ __forceinline__ void gridbar() {
    __syncthreads();
    if (threadIdx.x == 0) {
        __threadfence();                       // release: publish this block's writes
        unsigned gen = g_barGen;
        if (atomicAdd(&g_barCnt, 1u) == BB - 1u) {
            atomicExch(&g_barCnt, 0u);
            __threadfence();
            g_barGen = gen + 1u;
        } else {
            while (g_barGen == gen) { }
        }
    }
    __syncthreads();
}

// ---- math helpers: byte-identical to the R1/R2 kernels (rel_err was 0.0) ----
__device__ __forceinline__ float bil4(float s00, float s01, float s10, float s11,
                                      float w00, float w01, float w10, float w11) {
    return fmaf(s11, w11, fmaf(s10, w10, fmaf(s00, w00, __fmul_rn(s01, w01))));
}

struct BilW {
    int ix0, ix1, iy0, iy1;
    float w00, w01, w10, w11;
};

__device__ __forceinline__ BilW mkw(float x, float y) {
    BilW b;
    float x0f = floorf(x), y0f = floorf(y);
    float wx1 = __fsub_rn(x, x0f); float wx0 = __fsub_rn(1.0f, wx1);
    float wy1 = __fsub_rn(y, y0f); float wy0 = __fsub_rn(1.0f, wy1);
    int ix0 = (int)x0f; ix0 = ix0 < 0 ? 0 : (ix0 > WW-1 ? WW-1 : ix0);
    int iy0 = (int)y0f; iy0 = iy0 < 0 ? 0 : (iy0 > HH-1 ? HH-1 : iy0);
    b.ix0 = ix0; b.ix1 = (ix0+1 > WW-1) ? WW-1 : ix0+1;
    b.iy0 = iy0; b.iy1 = (iy0+1 > HH-1) ? HH-1 : iy0+1;
    b.w00 = __fmul_rn(wy0, wx0); b.w01 = __fmul_rn(wy0, wx1);
    b.w10 = __fmul_rn(wy1, wx0); b.w11 = __fmul_rn(wy1, wx1);
    return b;
}

__device__ __forceinline__ float on_at(const float* __restrict__ fb0,
                                       const float* __restrict__ fb1,
                                       float a0, float a1, int py, int px) {
    float xt = __fadd_rn((float)px, a0);
    float yt = __fadd_rn((float)py, a1);
    BilW b = mkw(xt, yt);
    float f00 = fb0[b.iy0*WW+b.ix0], f01 = fb0[b.iy0*WW+b.ix1];
    float f10 = fb0[b.iy1*WW+b.ix0], f11 = fb0[b.iy1*WW+b.ix1];
    float g00 = fb1[b.iy0*WW+b.ix0], g01 = fb1[b.iy0*WW+b.ix1];
    float g10 = fb1[b.iy1*WW+b.ix0], g11 = fb1[b.iy1*WW+b.ix1];
    float f0 = bil4(f00, f01, f10, f11, b.w00, b.w01, b.w10, b.w11);
    float f1 = bil4(g00, g01, g10, g11, b.w00, b.w01, b.w10, b.w11);
    float d0 = __fadd_rn(a0, f0), d1 = __fadd_rn(a1, f1);
    float diff = __fsqrt_rn(fmaf(d1, d1, __fmul_rn(d0, d0)));
    float m1 = __fsqrt_rn(fmaf(a1, a1, __fmul_rn(a0, a0)));
    float m2 = __fsqrt_rn(fmaf(f1, f1, __fmul_rn(f0, f0)));
    float mag = __fmul_rn(0.5f, __fadd_rn(m1, m2));
    return (diff <= fmaf(0.01f, mag, 0.1f)) ? 1.0f : 0.0f;
}

// ---------------- one persistent kernel, 2 grid barriers per step ----------------
__global__ void __launch_bounds__(TT, 4) k_linker(const float* __restrict__ ff,
                                                  const float* __restrict__ fb,
                                                  float* __restrict__ out) {
    const int tid  = threadIdx.x;
    const int b    = blockIdx.x;
    const int lane = tid & 31;
    const int wid  = tid >> 5;
    const int t    = b * TT + tid;         // slot id; also candidate id when < GG

    float* X  = out;
    float* Y  = out + SS*NSLOT;
    float* St = out + 2*SS*NSLOT;

    __shared__ int sh_cnt;
    __shared__ int sh_slotBase, sh_candBase, sh_nf;
    __shared__ int sh_w[4], sh_c[4];

    // ---- per-thread persistent state (slot t is touched ONLY by this thread) ----
    float myX, myY, mySt;
    {
        bool ing = t < GG;
        myX  = ing ? (float)(MARG + 4*(t % GXC)) : 0.0f;
        myY  = ing ? (float)(MARG + 4*(t / GXC)) : 0.0f;
        mySt = ing ? 0.0f : -1.0f;
        X[t] = myX; Y[t] = myY;            // row 0
    }

    for (int s = 0; s < SS - 1; s++) {
        const int p = s & 1;
        unsigned char* occ = g_occ[p];
        const float* ff0 = ff + (size_t)s * 2 * HWIMG;
        const float* ff1 = ff0 + HWIMG;
        const float* fb0 = fb + (size_t)s * 2 * HWIMG;
        const float* fb1 = fb0 + HWIMG;

        // ===== Phase A: clear idle occ buffer (own cell), advance own slot, mark occ =====
        if (t < GG) g_occ[p ^ 1][t] = 0;

        bool freeflag = true;                 // == (updated Start < 0)
        float xw = 0.0f, yw = 0.0f;
        if (mySt >= 0.0f) {
            BilW bw = mkw(myX, myY);
            float u00 = ff0[bw.iy0*WW+bw.ix0], u01 = ff0[bw.iy0*WW+bw.ix1];
            float u10 = ff0[bw.iy1*WW+bw.ix0], u11 = ff0[bw.iy1*WW+bw.ix1];
            float v00 = ff1[bw.iy0*WW+bw.ix0], v01 = ff1[bw.iy0*WW+bw.ix1];
            float v10 = ff1[bw.iy1*WW+bw.ix0], v11 = ff1[bw.iy1*WW+bw.ix1];
            float uvx = bil4(u00, u01, u10, u11, bw.w00, bw.w01, bw.w10, bw.w11);
            float uvy = bil4(v00, v01, v10, v11, bw.w00, bw.w01, bw.w10, bw.w11);
            float xt = __fadd_rn(myX, uvx);
            float yt = __fadd_rn(myY, uvy);
            bool marg = (xt > (float)MARG) && (yt > (float)MARG) &&
                        (xt < (float)(WW - MARG)) && (yt < (float)(HH - MARG));
            if (marg) {
                float on00 = (bw.w00 != 0.0f) ? on_at(fb0, fb1, u00, v00, bw.iy0, bw.ix0) : 0.0f;
                float on01 = (bw.w01 != 0.0f) ? on_at(fb0, fb1, u01, v01, bw.iy0, bw.ix1) : 0.0f;
                float on10 = (bw.w10 != 0.0f) ? on_at(fb0, fb1, u10, v10, bw.iy1, bw.ix0) : 0.0f;
                float on11 = (bw.w11 != 0.0f) ? on_at(fb0, fb1, u11, v11, bw.iy1, bw.ix1) : 0.0f;
                float onv = bil4(on00, on01, on10, on11, bw.w00, bw.w01, bw.w10, bw.w11);
                if (onv > 0.5f) {
                    freeflag = false;
                    xw = xt; yw = yt;
                    int oy = (int)yt, ox = (int)xt;
                    int iylo = (oy - 9) / 4; if (iylo < 0) iylo = 0;
                    int iyhi = (oy - 8) / 4; if (iyhi > GYC-1) iyhi = GYC-1;
                    int ixlo = (ox - 9) / 4; if (ixlo < 0) ixlo = 0;
                    int ixhi = (ox - 8) / 4; if (ixhi > GXC-1) ixhi = GXC-1;
                    for (int iy = iylo; iy <= iyhi; iy++)
                        for (int ix = ixlo; ix <= ixhi; ix++)
                            occ[iy*GXC + ix] = 1;          // idempotent
                }
            }
        }
        if (freeflag) mySt = -1.0f;
        myX = xw; myY = yw;
        X[(s+1)*NSLOT + t] = xw;
        Y[(s+1)*NSLOT + t] = yw;

        if (tid == 0) sh_cnt = 0;
        __syncthreads();
        unsigned amask = __ballot_sync(0xffffffffu, freeflag);
        if (lane == 0) atomicAdd(&sh_cnt, __popc(amask));
        __syncthreads();
        if (tid == 0) g_slotCnt[b] = sh_cnt;

        gridbar();   // occ marks + slot counts visible

        // ===== Phase B: my free-slot rank; ordered candidate compaction; totals =====
        if (tid == 0) { sh_slotBase = 0; sh_candBase = 0; sh_nf = 0; }
        __syncthreads();
        for (int i = tid; i < BB; i += TT) {
            int c = __ldcg(&g_slotCnt[i]);
            atomicAdd(&sh_nf, c);
            if (i < b) atomicAdd(&sh_slotBase, c);
        }
        unsigned smask = __ballot_sync(0xffffffffu, freeflag);
        if (lane == 0) sh_w[wid] = __popc(smask);

        bool cf = false;
        unsigned cmask = 0;
        if (b < NCANDB) {
            if (t < GG) cf = (__ldcg(&occ[t]) == 0);
            // candidate base for this block: zeros in occ[0 .. b*TT)
            int pre = b * TT;
            int zbits = 0;
            for (int i = tid * 16; i < pre; i += TT * 16) {
                uint4 v = __ldcg((const uint4*)(occ + i));
                zbits += __popc(__vcmpeq4(v.x, 0u)) + __popc(__vcmpeq4(v.y, 0u))
                       + __popc(__vcmpeq4(v.z, 0u)) + __popc(__vcmpeq4(v.w, 0u));
            }
            zbits = __reduce_add_sync(0xffffffffu, zbits);
            if (lane == 0 && zbits) atomicAdd(&sh_candBase, zbits >> 3);
            cmask = __ballot_sync(0xffffffffu, cf);
            if (lane == 0) sh_c[wid] = __popc(cmask);
        }
        __syncthreads();
        if (tid == 0) {
            int run = sh_slotBase;
            for (int i = 0; i < 4; i++) { int c = sh_w[i]; sh_w[i] = run; run += c; }
            if (b < NCANDB) {
                int crun = sh_candBase;
                for (int i = 0; i < 4; i++) { int c = sh_c[i]; sh_c[i] = crun; crun += c; }
                if (b == NCANDB - 1) g_nc = crun;     // total free candidates
            }
        }
        __syncthreads();
        int myrank = -1;
        if (freeflag) myrank = sh_w[wid] + __popc(smask & ((1u << lane) - 1u));
        if (cf)
            g_candList[sh_c[wid] + __popc(cmask & ((1u << lane) - 1u))] = t;
        int nf = sh_nf;

        gridbar();   // candList + g_nc visible

        // ===== Phase C': self-birth (k-th free slot takes k-th free candidate) =====
        int nc = __ldcg(&g_nc);
        int m = nf < nc ? nf : nc;
        if (myrank >= 0 && myrank < m) {
            int g = __ldcg(&g_candList[myrank]);
            int iy = g / GXC, ix = g % GXC;
            myX = (float)(MARG + 4*ix);
            myY = (float)(MARG + 4*iy);
            mySt = (float)(s + 1);
            X[(s+1)*NSLOT + t] = myX;
            Y[(s+1)*NSLOT + t] = myY;
        }
        // no barrier: next Phase A reads only thread-own state
    }

    St[t] = mySt;
    if (t < GG) g_occ[0][t] = 0;   // last step used buffer 0; restore zero-invariant for replay
}

extern "C" void kernel_launch(void* const* d_in, const int* in_sizes, int n_in,
                              void* d_out, int out_size) {
    (void)in_sizes; (void)n_in; (void)out_size;
    const float* ff = (const float*)d_in[0];
    const float* fb = (const float*)d_in[1];
    float* out = (float*)d_out;
    k_linker<<<BB, TT>>>(ff, fb, out);
}

// round 5
// speedup vs baseline: 1.1748x; 1.0555x over previous
#include <cuda_runtime.h>

// Problem constants (fixed by setup_inputs: H=480, W=1024, S=32, margin=10, step=4)
#define HH     480
#define WW     1024
#define SS     32
#define HWIMG  (HH*WW)          // 491520
#define NSLOT  61440            // 2*H*W/step^2
#define GXC    252
#define GYC    116
#define GG     (GXC*GYC)        // 29232
#define MARG   10
#define BB     240              // persistent grid: 240 blocks x 256 = NSLOT threads
#define TT     256
#define NWARP  (TT/32)
#define NCANDB 115              // ceil(GG / TT)
#define WPI    (HWIMG/32)       // 15360 bitmask words per step

// Scratch (device globals; no allocations allowed)
__device__ __align__(16) unsigned char g_occ[2][GG];  // double-buffered by parity; zero at load & exit
__device__ unsigned g_on[(SS-1)*WPI];                 // precomputed fwd-bwd consistency bitmask
__device__ int g_candList[GG];
__device__ int g_slotCnt[BB];
__device__ int g_nc;
__device__ unsigned g_barCnt = 0;
__device__ volatile unsigned g_barGen = 0;

__device__ __forceinline__ void gridbar() {
    __syncthreads();
    if (threadIdx.x == 0) {
        __threadfence();                       // release: publish this block's writes
        unsigned gen = g_barGen;
        if (atomicAdd(&g_barCnt, 1u) == BB - 1u) {
            atomicExch(&g_barCnt, 0u);
            __threadfence();
            g_barGen = gen + 1u;
        } else {
            while (g_barGen == gen) { }
        }
    }
    __syncthreads();
}

// ---- math helpers: byte-identical to R1/R2/R3 (rel_err was 0.0) ----
__device__ __forceinline__ float bil4(float s00, float s01, float s10, float s11,
                                      float w00, float w01, float w10, float w11) {
    return fmaf(s11, w11, fmaf(s10, w10, fmaf(s00, w00, __fmul_rn(s01, w01))));
}

struct BilW {
    int ix0, ix1, iy0, iy1;
    float w00, w01, w10, w11;
};

__device__ __forceinline__ BilW mkw(float x, float y) {
    BilW b;
    float x0f = floorf(x), y0f = floorf(y);
    float wx1 = __fsub_rn(x, x0f); float wx0 = __fsub_rn(1.0f, wx1);
    float wy1 = __fsub_rn(y, y0f); float wy0 = __fsub_rn(1.0f, wy1);
    int ix0 = (int)x0f; ix0 = ix0 < 0 ? 0 : (ix0 > WW-1 ? WW-1 : ix0);
    int iy0 = (int)y0f; iy0 = iy0 < 0 ? 0 : (iy0 > HH-1 ? HH-1 : iy0);
    b.ix0 = ix0; b.ix1 = (ix0+1 > WW-1) ? WW-1 : ix0+1;
    b.iy0 = iy0; b.iy1 = (iy0+1 > HH-1) ? HH-1 : iy0+1;
    b.w00 = __fmul_rn(wy0, wx0); b.w01 = __fmul_rn(wy0, wx1);
    b.w10 = __fmul_rn(wy1, wx0); b.w11 = __fmul_rn(wy1, wx1);
    return b;
}

__device__ __forceinline__ float on_at(const float* __restrict__ fb0,
                                       const float* __restrict__ fb1,
                                       float a0, float a1, int py, int px) {
    float xt = __fadd_rn((float)px, a0);
    float yt = __fadd_rn((float)py, a1);
    BilW b = mkw(xt, yt);
    float f00 = fb0[b.iy0*WW+b.ix0], f01 = fb0[b.iy0*WW+b.ix1];
    float f10 = fb0[b.iy1*WW+b.ix0], f11 = fb0[b.iy1*WW+b.ix1];
    float g00 = fb1[b.iy0*WW+b.ix0], g01 = fb1[b.iy0*WW+b.ix1];
    float g10 = fb1[b.iy1*WW+b.ix0], g11 = fb1[b.iy1*WW+b.ix1];
    float f0 = bil4(f00, f01, f10, f11, b.w00, b.w01, b.w10, b.w11);
    float f1 = bil4(g00, g01, g10, g11, b.w00, b.w01, b.w10, b.w11);
    float d0 = __fadd_rn(a0, f0), d1 = __fadd_rn(a1, f1);
    float diff = __fsqrt_rn(fmaf(d1, d1, __fmul_rn(d0, d0)));
    float m1 = __fsqrt_rn(fmaf(a1, a1, __fmul_rn(a0, a0)));
    float m2 = __fsqrt_rn(fmaf(f1, f1, __fmul_rn(f0, f0)));
    float mag = __fmul_rn(0.5f, __fadd_rn(m1, m2));
    return (diff <= fmaf(0.01f, mag, 0.1f)) ? 1.0f : 0.0f;
}

// ---------------- precompute: dense fwd-bwd consistency bitmask for ALL steps ----------------
__global__ void __launch_bounds__(256) k_onmask(const float* __restrict__ ff,
                                                const float* __restrict__ fb) {
    int s = blockIdx.y;
    int p = blockIdx.x * 256 + threadIdx.x;        // pixel index
    const float* ff0 = ff + (size_t)s * 2 * HWIMG;
    const float* ff1 = ff0 + HWIMG;
    const float* fb0 = fb + (size_t)s * 2 * HWIMG;
    const float* fb1 = fb0 + HWIMG;
    float a0 = ff0[p], a1 = ff1[p];
    int py = p >> 10;                              // WW == 1024
    int px = p & 1023;
    float on = on_at(fb0, fb1, a0, a1, py, px);
    unsigned m = __ballot_sync(0xffffffffu, on != 0.0f);
    if ((threadIdx.x & 31) == 0) g_on[s*WPI + (p >> 5)] = m;
}

// ---------------- persistent serial kernel, 2 grid barriers per step ----------------
__global__ void __launch_bounds__(TT, 2) k_linker(const float* __restrict__ ff,
                                                  float* __restrict__ out) {
    const int tid  = threadIdx.x;
    const int b    = blockIdx.x;
    const int lane = tid & 31;
    const int wid  = tid >> 5;
    const int t    = b * TT + tid;         // slot id; also candidate id when < GG

    float* X  = out;
    float* Y  = out + SS*NSLOT;
    float* St = out + 2*SS*NSLOT;

    __shared__ int sh_cnt;
    __shared__ int sh_slotBase, sh_candBase, sh_nf;
    __shared__ int sh_w[NWARP], sh_c[NWARP];

    // ---- per-thread persistent state (slot t is touched ONLY by this thread) ----
    float myX, myY, mySt;
    {
        bool ing = t < GG;
        myX  = ing ? (float)(MARG + 4*(t % GXC)) : 0.0f;
        myY  = ing ? (float)(MARG + 4*(t / GXC)) : 0.0f;
        mySt = ing ? 0.0f : -1.0f;
        X[t] = myX; Y[t] = myY;            // row 0
    }

    for (int s = 0; s < SS - 1; s++) {
        const int p = s & 1;
        unsigned char* occ = g_occ[p];
        const float* ff0 = ff + (size_t)s * 2 * HWIMG;
        const float* ff1 = ff0 + HWIMG;
        const unsigned* onw = g_on + s*WPI;

        // ===== Phase A: clear idle occ buffer (own cell), advance own slot, mark occ =====
        if (t < GG) g_occ[p ^ 1][t] = 0;

        bool freeflag = true;                 // == (updated Start < 0)
        float xw = 0.0f, yw = 0.0f;
        if (mySt >= 0.0f) {
            BilW bw = mkw(myX, myY);
            float u00 = ff0[bw.iy0*WW+bw.ix0], u01 = ff0[bw.iy0*WW+bw.ix1];
            float u10 = ff0[bw.iy1*WW+bw.ix0], u11 = ff0[bw.iy1*WW+bw.ix1];
            float v00 = ff1[bw.iy0*WW+bw.ix0], v01 = ff1[bw.iy0*WW+bw.ix1];
            float v10 = ff1[bw.iy1*WW+bw.ix0], v11 = ff1[bw.iy1*WW+bw.ix1];
            float uvx = bil4(u00, u01, u10, u11, bw.w00, bw.w01, bw.w10, bw.w11);
            float uvy = bil4(v00, v01, v10, v11, bw.w00, bw.w01, bw.w10, bw.w11);
            float xt = __fadd_rn(myX, uvx);
            float yt = __fadd_rn(myY, uvy);
            bool marg = (xt > (float)MARG) && (yt > (float)MARG) &&
                        (xt < (float)(WW - MARG)) && (yt < (float)(HH - MARG));
            if (marg) {
                // bitmask probes reconstruct exactly 0.0f/1.0f (bit-identical to on_at)
                float on00 = (float)((onw[(bw.iy0<<5) + (bw.ix0>>5)] >> (bw.ix0&31)) & 1u);
                float on01 = (float)((onw[(bw.iy0<<5) + (bw.ix1>>5)] >> (bw.ix1&31)) & 1u);
                float on10 = (float)((onw[(bw.iy1<<5) + (bw.ix0>>5)] >> (bw.ix0&31)) & 1u);
                float on11 = (float)((onw[(bw.iy1<<5) + (bw.ix1>>5)] >> (bw.ix1&31)) & 1u);
                float onv = bil4(on00, on01, on10, on11, bw.w00, bw.w01, bw.w10, bw.w11);
                if (onv > 0.5f) {
                    freeflag = false;
                    xw = xt; yw = yt;
                    int oy = (int)yt, ox = (int)xt;
                    int iylo = (oy - 9) / 4; if (iylo < 0) iylo = 0;
                    int iyhi = (oy - 8) / 4; if (iyhi > GYC-1) iyhi = GYC-1;
                    int ixlo = (ox - 9) / 4; if (ixlo < 0) ixlo = 0;
                    int ixhi = (ox - 8) / 4; if (ixhi > GXC-1) ixhi = GXC-1;
                    for (int iy = iylo; iy <= iyhi; iy++)
                        for (int ix = ixlo; ix <= ixhi; ix++)
                            occ[iy*GXC + ix] = 1;          // idempotent
                }
            }
        }
        if (freeflag) mySt = -1.0f;
        myX = xw; myY = yw;
        X[(s+1)*NSLOT + t] = xw;
        Y[(s+1)*NSLOT + t] = yw;

        if (tid == 0) sh_cnt = 0;
        __syncthreads();
        unsigned amask = __ballot_sync(0xffffffffu, freeflag);
        if (lane == 0) atomicAdd(&sh_cnt, __popc(amask));
        __syncthreads();
        if (tid == 0) g_slotCnt[b] = sh_cnt;

        gridbar();   // occ marks + slot counts visible

        // ===== Phase B: my free-slot rank; ordered candidate compaction; totals =====
        if (tid == 0) { sh_slotBase = 0; sh_candBase = 0; sh_nf = 0; }
        __syncthreads();
        {
            // ALL threads execute these collectives (fix for R4 deadlock:
            // partial-warp entry into __reduce_add_sync is illegal)
            int c = (tid < BB) ? __ldcg(&g_slotCnt[tid]) : 0;
            int tot = __reduce_add_sync(0xffffffffu, c);
            int pre = __reduce_add_sync(0xffffffffu, (tid < b) ? c : 0);
            if (lane == 0) {
                atomicAdd(&sh_nf, tot);
                if (pre) atomicAdd(&sh_slotBase, pre);
            }
        }
        unsigned smask = __ballot_sync(0xffffffffu, freeflag);
        if (lane == 0) sh_w[wid] = __popc(smask);

        bool cf = false;
        unsigned cmask = 0;
        if (b < NCANDB) {
            if (t < GG) cf = (__ldcg(&occ[t]) == 0);
            // candidate base for this block: zeros in occ[0 .. b*TT)
            int pre = b * TT;
            int zbits = 0;
            for (int i = tid * 16; i < pre; i += TT * 16) {
                uint4 v = __ldcg((const uint4*)(occ + i));
                zbits += __popc(__vcmpeq4(v.x, 0u)) + __popc(__vcmpeq4(v.y, 0u))
                       + __popc(__vcmpeq4(v.z, 0u)) + __popc(__vcmpeq4(v.w, 0u));
            }
            zbits = __reduce_add_sync(0xffffffffu, zbits);
            if (lane == 0 && zbits) atomicAdd(&sh_candBase, zbits >> 3);
            cmask = __ballot_sync(0xffffffffu, cf);
            if (lane == 0) sh_c[wid] = __popc(cmask);
        }
        __syncthreads();
        if (tid == 0) {
            int run = sh_slotBase;
            for (int i = 0; i < NWARP; i++) { int c = sh_w[i]; sh_w[i] = run; run += c; }
            if (b < NCANDB) {
                int crun = sh_candBase;
                for (int i = 0; i < NWARP; i++) { int c = sh_c[i]; sh_c[i] = crun; crun += c; }
                if (b == NCANDB - 1) g_nc = crun;     // total free candidates
            }
        }
        __syncthreads();
        int myrank = -1;
        if (freeflag) myrank = sh_w[wid] + __popc(smask & ((1u << lane) - 1u));
        if (cf)
            g_candList[sh_c[wid] + __popc(cmask & ((1u << lane) - 1u))] = t;
        int nf = sh_nf;

        gridbar();   // candList + g_nc visible

        // ===== Phase C': self-birth (k-th free slot takes k-th free candidate) =====
        int nc = __ldcg(&g_nc);
        int m = nf < nc ? nf : nc;
        if (myrank >= 0 && myrank < m) {
            int g = __ldcg(&g_candList[myrank]);
            int iy = g / GXC, ix = g % GXC;
            myX = (float)(MARG + 4*ix);
            myY = (float)(MARG + 4*iy);
            mySt = (float)(s + 1);
            X[(s+1)*NSLOT + t] = myX;
            Y[(s+1)*NSLOT + t] = myY;
        }
        // no barrier: next Phase A reads only thread-own state
    }

    St[t] = mySt;
    if (t < GG) g_occ[0][t] = 0;   // last step used buffer 0; restore zero-invariant for replay
}

extern "C" void kernel_launch(void* const* d_in, const int* in_sizes, int n_in,
                              void* d_out, int out_size) {
    (void)in_sizes; (void)n_in; (void)out_size;
    const float* ff = (const float*)d_in[0];
    const float* fb = (const float*)d_in[1];
    float* out = (float*)d_out;
    dim3 g1(HWIMG/256, SS-1);
    k_onmask<<<g1, 256>>>(ff, fb);
    k_linker<<<BB, TT>>>(ff, out);
}

// round 6
// speedup vs baseline: 1.1958x; 1.0179x over previous
#include <cuda_runtime.h>

// Problem constants (fixed by setup_inputs: H=480, W=1024, S=32, margin=10, step=4)
#define HH     480
#define WW     1024
#define SS     32
#define HWIMG  (HH*WW)          // 491520
#define NSLOT  61440            // 2*H*W/step^2
#define GXC    252
#define GYC    116
#define GG     (GXC*GYC)        // 29232
#define MARG   10
#define BB     240              // persistent grid: 240 blocks x 256 = NSLOT threads
#define TT     256
#define NWARP  (TT/32)
#define NCANDB 115              // ceil(GG / TT)
#define WPI    (HWIMG/32)       // 15360 bitmask words per step
#define NSUB   8
#define SUBQ   (BB/NSUB)        // 30

// Scratch (device globals; no allocations allowed)
__device__ __align__(16) unsigned char g_occ[2][GG];  // double-buffered by parity; zero at load & exit
__device__ unsigned g_on[(SS-1)*WPI];                 // precomputed fwd-bwd consistency bitmask
__device__ int g_candList[GG];
__device__ int g_slotCnt[BB];
__device__ int g_nc;

// ---- grid barrier state: every hot word on its OWN 128B line ----
struct __align__(128) PadCnt { unsigned v; unsigned pad[31]; };
__device__ PadCnt g_barSub[NSUB];                     // zero-init
__device__ PadCnt g_barMaster;                        // zero-init
__device__ __align__(128) volatile unsigned g_barGen; // zero-init; monotonically increasing

__device__ __forceinline__ void gridbar() {
    __syncthreads();
    if (threadIdx.x == 0) {
        __threadfence();                       // release: publish this block's writes
        unsigned gen = g_barGen;               // read BEFORE arrival (else lost-release race)
        bool last = false;
        if (atomicAdd(&g_barSub[blockIdx.x & (NSUB - 1)].v, 1u) == SUBQ - 1u) {
            if (atomicAdd(&g_barMaster.v, 1u) == NSUB - 1u) last = true;
        }
        if (last) {
            // all BB blocks have arrived; nobody touches counters until gen bumps
            g_barMaster.v = 0;
            #pragma unroll
            for (int i = 0; i < NSUB; i++) g_barSub[i].v = 0;
            __threadfence();
            g_barGen = gen + 1u;
        } else {
            while (g_barGen == gen) { }
        }
    }
    __syncthreads();
}

// ---- math helpers: byte-identical to R1..R5 (rel_err was 0.0) ----
__device__ __forceinline__ float bil4(float s00, float s01, float s10, float s11,
                                      float w00, float w01, float w10, float w11) {
    return fmaf(s11, w11, fmaf(s10, w10, fmaf(s00, w00, __fmul_rn(s01, w01))));
}

struct BilW {
    int ix0, ix1, iy0, iy1;
    float w00, w01, w10, w11;
};

__device__ __forceinline__ BilW mkw(float x, float y) {
    BilW b;
    float x0f = floorf(x), y0f = floorf(y);
    float wx1 = __fsub_rn(x, x0f); float wx0 = __fsub_rn(1.0f, wx1);
    float wy1 = __fsub_rn(y, y0f); float wy0 = __fsub_rn(1.0f, wy1);
    int ix0 = (int)x0f; ix0 = ix0 < 0 ? 0 : (ix0 > WW-1 ? WW-1 : ix0);
    int iy0 = (int)y0f; iy0 = iy0 < 0 ? 0 : (iy0 > HH-1 ? HH-1 : iy0);
    b.ix0 = ix0; b.ix1 = (ix0+1 > WW-1) ? WW-1 : ix0+1;
    b.iy0 = iy0; b.iy1 = (iy0+1 > HH-1) ? HH-1 : iy0+1;
    b.w00 = __fmul_rn(wy0, wx0); b.w01 = __fmul_rn(wy0, wx1);
    b.w10 = __fmul_rn(wy1, wx0); b.w11 = __fmul_rn(wy1, wx1);
    return b;
}

__device__ __forceinline__ float on_at(const float* __restrict__ fb0,
                                       const float* __restrict__ fb1,
                                       float a0, float a1, int py, int px) {
    float xt = __fadd_rn((float)px, a0);
    float yt = __fadd_rn((float)py, a1);
    BilW b = mkw(xt, yt);
    float f00 = fb0[b.iy0*WW+b.ix0], f01 = fb0[b.iy0*WW+b.ix1];
    float f10 = fb0[b.iy1*WW+b.ix0], f11 = fb0[b.iy1*WW+b.ix1];
    float g00 = fb1[b.iy0*WW+b.ix0], g01 = fb1[b.iy0*WW+b.ix1];
    float g10 = fb1[b.iy1*WW+b.ix0], g11 = fb1[b.iy1*WW+b.ix1];
    float f0 = bil4(f00, f01, f10, f11, b.w00, b.w01, b.w10, b.w11);
    float f1 = bil4(g00, g01, g10, g11, b.w00, b.w01, b.w10, b.w11);
    float d0 = __fadd_rn(a0, f0), d1 = __fadd_rn(a1, f1);
    float diff = __fsqrt_rn(fmaf(d1, d1, __fmul_rn(d0, d0)));
    float m1 = __fsqrt_rn(fmaf(a1, a1, __fmul_rn(a0, a0)));
    float m2 = __fsqrt_rn(fmaf(f1, f1, __fmul_rn(f0, f0)));
    float mag = __fmul_rn(0.5f, __fadd_rn(m1, m2));
    return (diff <= fmaf(0.01f, mag, 0.1f)) ? 1.0f : 0.0f;
}

// ---------------- precompute: dense fwd-bwd consistency bitmask for ALL steps ----------------
// 2 pixels per thread (p and p+HWIMG/2) for doubled memory-level parallelism.
__global__ void __launch_bounds__(256) k_onmask(const float* __restrict__ ff,
                                                const float* __restrict__ fb) {
    int s = blockIdx.y;
    int p = blockIdx.x * 256 + threadIdx.x;        // first pixel
    int q = p + HWIMG/2;                           // second pixel (independent word)
    const float* ff0 = ff + (size_t)s * 2 * HWIMG;
    const float* ff1 = ff0 + HWIMG;
    const float* fb0 = fb + (size_t)s * 2 * HWIMG;
    const float* fb1 = fb0 + HWIMG;
    float a0 = ff0[p], a1 = ff1[p];
    float b0 = ff0[q], b1 = ff1[q];
    float on1 = on_at(fb0, fb1, a0, a1, p >> 10, p & 1023);
    float on2 = on_at(fb0, fb1, b0, b1, q >> 10, q & 1023);
    unsigned m1 = __ballot_sync(0xffffffffu, on1 != 0.0f);
    unsigned m2 = __ballot_sync(0xffffffffu, on2 != 0.0f);
    if ((threadIdx.x & 31) == 0) {
        g_on[s*WPI + (p >> 5)] = m1;
        g_on[s*WPI + (q >> 5)] = m2;
    }
}

// ---------------- persistent serial kernel, 2 grid barriers per step ----------------
__global__ void __launch_bounds__(TT, 2) k_linker(const float* __restrict__ ff,
                                                  float* __restrict__ out) {
    const int tid  = threadIdx.x;
    const int b    = blockIdx.x;
    const int lane = tid & 31;
    const int wid  = tid >> 5;
    const int t    = b * TT + tid;         // slot id; also candidate id when < GG

    float* X  = out;
    float* Y  = out + SS*NSLOT;
    float* St = out + 2*SS*NSLOT;

    __shared__ int sh_cnt;
    __shared__ int sh_slotBase, sh_candBase, sh_nf;
    __shared__ int sh_w[NWARP], sh_c[NWARP];

    // ---- per-thread persistent state (slot t is touched ONLY by this thread) ----
    float myX, myY, mySt;
    {
        bool ing = t < GG;
        myX  = ing ? (float)(MARG + 4*(t % GXC)) : 0.0f;
        myY  = ing ? (float)(MARG + 4*(t / GXC)) : 0.0f;
        mySt = ing ? 0.0f : -1.0f;
        X[t] = myX; Y[t] = myY;            // row 0
    }

    for (int s = 0; s < SS - 1; s++) {
        const int p = s & 1;
        unsigned char* occ = g_occ[p];
        const float* ff0 = ff + (size_t)s * 2 * HWIMG;
        const float* ff1 = ff0 + HWIMG;
        const unsigned* onw = g_on + s*WPI;

        // ===== Phase A: clear idle occ buffer (own cell), advance own slot, mark occ =====
        if (t < GG) g_occ[p ^ 1][t] = 0;

        bool freeflag = true;                 // == (updated Start < 0)
        float xw = 0.0f, yw = 0.0f;
        if (mySt >= 0.0f) {
            BilW bw = mkw(myX, myY);
            float u00 = ff0[bw.iy0*WW+bw.ix0], u01 = ff0[bw.iy0*WW+bw.ix1];
            float u10 = ff0[bw.iy1*WW+bw.ix0], u11 = ff0[bw.iy1*WW+bw.ix1];
            float v00 = ff1[bw.iy0*WW+bw.ix0], v01 = ff1[bw.iy0*WW+bw.ix1];
            float v10 = ff1[bw.iy1*WW+bw.ix0], v11 = ff1[bw.iy1*WW+bw.ix1];
            float uvx = bil4(u00, u01, u10, u11, bw.w00, bw.w01, bw.w10, bw.w11);
            float uvy = bil4(v00, v01, v10, v11, bw.w00, bw.w01, bw.w10, bw.w11);
            float xt = __fadd_rn(myX, uvx);
            float yt = __fadd_rn(myY, uvy);
            bool marg = (xt > (float)MARG) && (yt > (float)MARG) &&
                        (xt < (float)(WW - MARG)) && (yt < (float)(HH - MARG));
            if (marg) {
                // bitmask probes reconstruct exactly 0.0f/1.0f (bit-identical to on_at)
                float on00 = (float)((onw[(bw.iy0<<5) + (bw.ix0>>5)] >> (bw.ix0&31)) & 1u);
                float on01 = (float)((onw[(bw.iy0<<5) + (bw.ix1>>5)] >> (bw.ix1&31)) & 1u);
                float on10 = (float)((onw[(bw.iy1<<5) + (bw.ix0>>5)] >> (bw.ix0&31)) & 1u);
                float on11 = (float)((onw[(bw.iy1<<5) + (bw.ix1>>5)] >> (bw.ix1&31)) & 1u);
                float onv = bil4(on00, on01, on10, on11, bw.w00, bw.w01, bw.w10, bw.w11);
                if (onv > 0.5f) {
                    freeflag = false;
                    xw = xt; yw = yt;
                    int oy = (int)yt, ox = (int)xt;
                    int iylo = (oy - 9) / 4; if (iylo < 0) iylo = 0;
                    int iyhi = (oy - 8) / 4; if (iyhi > GYC-1) iyhi = GYC-1;
                    int ixlo = (ox - 9) / 4; if (ixlo < 0) ixlo = 0;
                    int ixhi = (ox - 8) / 4; if (ixhi > GXC-1) ixhi = GXC-1;
                    for (int iy = iylo; iy <= iyhi; iy++)
                        for (int ix = ixlo; ix <= ixhi; ix++)
                            occ[iy*GXC + ix] = 1;          // idempotent
                }
            }
        }
        if (freeflag) mySt = -1.0f;
        myX = xw; myY = yw;
        X[(s+1)*NSLOT + t] = xw;
        Y[(s+1)*NSLOT + t] = yw;

        if (tid == 0) sh_cnt = 0;
        __syncthreads();
        unsigned amask = __ballot_sync(0xffffffffu, freeflag);
        if (lane == 0) atomicAdd(&sh_cnt, __popc(amask));
        __syncthreads();
        if (tid == 0) g_slotCnt[b] = sh_cnt;

        gridbar();   // occ marks + slot counts visible

        // ===== Phase B: my free-slot rank; ordered candidate compaction; totals =====
        if (tid == 0) { sh_slotBase = 0; sh_candBase = 0; sh_nf = 0; }
        __syncthreads();
        {
            // ALL threads execute these collectives (partial-warp entry is illegal)
            int c = (tid < BB) ? __ldcg(&g_slotCnt[tid]) : 0;
            int tot = __reduce_add_sync(0xffffffffu, c);
            int pre = __reduce_add_sync(0xffffffffu, (tid < b) ? c : 0);
            if (lane == 0) {
                atomicAdd(&sh_nf, tot);
                if (pre) atomicAdd(&sh_slotBase, pre);
            }
        }
        unsigned smask = __ballot_sync(0xffffffffu, freeflag);
        if (lane == 0) sh_w[wid] = __popc(smask);

        bool cf = false;
        unsigned cmask = 0;
        if (b < NCANDB) {
            if (t < GG) cf = (__ldcg(&occ[t]) == 0);
            // candidate base for this block: zeros in occ[0 .. b*TT)
            int pre = b * TT;
            int zbits = 0;
            for (int i = tid * 16; i < pre; i += TT * 16) {
                uint4 v = __ldcg((const uint4*)(occ + i));
                zbits += __popc(__vcmpeq4(v.x, 0u)) + __popc(__vcmpeq4(v.y, 0u))
                       + __popc(__vcmpeq4(v.z, 0u)) + __popc(__vcmpeq4(v.w, 0u));
            }
            zbits = __reduce_add_sync(0xffffffffu, zbits);
            if (lane == 0 && zbits) atomicAdd(&sh_candBase, zbits >> 3);
            cmask = __ballot_sync(0xffffffffu, cf);
            if (lane == 0) sh_c[wid] = __popc(cmask);
        }
        __syncthreads();
        if (tid == 0) {
            int run = sh_slotBase;
            for (int i = 0; i < NWARP; i++) { int c = sh_w[i]; sh_w[i] = run; run += c; }
            if (b < NCANDB) {
                int crun = sh_candBase;
                for (int i = 0; i < NWARP; i++) { int c = sh_c[i]; sh_c[i] = crun; crun += c; }
                if (b == NCANDB - 1) g_nc = crun;     // total free candidates
            }
        }
        __syncthreads();
        int myrank = -1;
        if (freeflag) myrank = sh_w[wid] + __popc(smask & ((1u << lane) - 1u));
        if (cf)
            g_candList[sh_c[wid] + __popc(cmask & ((1u << lane) - 1u))] = t;
        int nf = sh_nf;

        gridbar();   // candList + g_nc visible

        // ===== Phase C': self-birth (k-th free slot takes k-th free candidate) =====
        int nc = __ldcg(&g_nc);
        int m = nf < nc ? nf : nc;
        if (myrank >= 0 && myrank < m) {
            int g = __ldcg(&g_candList[myrank]);
            int iy = g / GXC, ix = g % GXC;
            myX = (float)(MARG + 4*ix);
            myY = (float)(MARG + 4*iy);
            mySt = (float)(s + 1);
            X[(s+1)*NSLOT + t] = myX;
            Y[(s+1)*NSLOT + t] = myY;
        }
        // no barrier: next Phase A reads only thread-own state
    }

    St[t] = mySt;
    if (t < GG) g_occ[0][t] = 0;   // last step used buffer 0; restore zero-invariant for replay
}

extern "C" void kernel_launch(void* const* d_in, const int* in_sizes, int n_in,
                              void* d_out, int out_size) {
    (void)in_sizes; (void)n_in; (void)out_size;
    const float* ff = (const float*)d_in[0];
    const float* fb = (const float*)d_in[1];
    float* out = (float*)d_out;
    dim3 g1(HWIMG/512, SS-1);
    k_onmask<<<g1, 256>>>(ff, fb);
    k_linker<<<BB, TT>>>(ff, out);
}